// round 3
// baseline (speedup 1.0000x reference)
#include <cuda_runtime.h>
#include <cstddef>

#define NN 50000
#define NE 600000
#define DD 128
#define DOUT 32
#define NG 64

// -------- scratch (device globals: allocation-free) --------
__device__ float g_deg[NN];
__device__ float g_dinv[NN];
__device__ int   g_src[NE];
__device__ int   g_dst[NE];
__device__ float g_norm[NE];
__device__ __align__(16) float g_bufA[(size_t)NN * DD];   // hW scratch (gather source)
__device__ __align__(16) float g_bufB[(size_t)NN * DD];   // running h (scatter target)
__device__ __align__(16) float g_pool[NG * DD];
__device__ float g_cnt[NG];

// -------- prep kernels --------
__global__ void k_init() {
    int i = blockIdx.x * blockDim.x + threadIdx.x;
    if (i < NN) g_deg[i] = 1.0f;          // self-loop contributes 1 to degree
    if (i < NG * DD) g_pool[i] = 0.0f;
    if (i < NG) g_cnt[i] = 0.0f;
}

__global__ void k_edges(const int* __restrict__ ei) {
    int e = blockIdx.x * blockDim.x + threadIdx.x;
    if (e >= NE) return;
    int s = ei[e];
    int d = ei[NE + e];
    g_src[e] = s;
    g_dst[e] = d;
    atomicAdd(&g_deg[d], 1.0f);
}

__global__ void k_dinv(const int* __restrict__ batch) {
    int n = blockIdx.x * blockDim.x + threadIdx.x;
    if (n >= NN) return;
    g_dinv[n] = rsqrtf(g_deg[n]);         // deg >= 1 always (self-loop)
    atomicAdd(&g_cnt[batch[n]], 1.0f);
}

__global__ void k_norm() {
    int e = blockIdx.x * blockDim.x + threadIdx.x;
    if (e >= NE) return;
    g_norm[e] = g_dinv[g_src[e]] * g_dinv[g_dst[e]];
}

// -------- GEMM: hW = A @ W  (A:[NN,128], W:[128,128])
// Epilogue writes hW -> g_bufA and acc-init -> g_bufB:
//   acc[n][c] = hW[n][c]*dinv[n]^2 + bias[c]   (self-loop message + bias)
// Aliasing g_bufB as input (layers 2..4) is safe: each block writes exactly
// the rows it alone reads, and all its global reads finish before epilogue.
template <bool FIRST>
__global__ __launch_bounds__(256) void k_gemm(const float* __restrict__ X,
                                              const float* __restrict__ W,
                                              const float* __restrict__ bias) {
    const float* A = FIRST ? X : (const float*)g_bufB;
    __shared__ float As[64][33];                         // [m][k], +1 pad
    __shared__ __align__(16) float Bs[32][DD];           // [k][n]
    int t  = threadIdx.x;
    int m0 = blockIdx.x * 64;
    int tn = (t & 31) << 2;      // 4 output cols
    int tm = (t >> 5) << 3;      // 8 output rows (uniform per warp -> A broadcast)

    float ac[8][4];
#pragma unroll
    for (int i = 0; i < 8; i++)
#pragma unroll
        for (int j = 0; j < 4; j++) ac[i][j] = 0.0f;

    for (int k0 = 0; k0 < DD; k0 += 32) {
#pragma unroll
        for (int i = 0; i < 2; i++) {                    // A tile 64x32
            int idx = t + i * 256;
            int r = idx >> 3, c4 = (idx & 7) << 2;
            int gr = m0 + r;
            float4 v = make_float4(0.f, 0.f, 0.f, 0.f);
            if (gr < NN) v = *(const float4*)(A + (size_t)gr * DD + k0 + c4);
            As[r][c4 + 0] = v.x; As[r][c4 + 1] = v.y;
            As[r][c4 + 2] = v.z; As[r][c4 + 3] = v.w;
        }
#pragma unroll
        for (int i = 0; i < 4; i++) {                    // W tile 32x128
            int idx = t + i * 256;
            int kr = idx >> 5, c4 = (idx & 31) << 2;
            *(float4*)(&Bs[kr][c4]) = *(const float4*)(W + (size_t)(k0 + kr) * DD + c4);
        }
        __syncthreads();
#pragma unroll
        for (int k = 0; k < 32; k++) {
            float4 bv = *(const float4*)(&Bs[k][tn]);
#pragma unroll
            for (int i = 0; i < 8; i++) {
                float a = As[tm + i][k];
                ac[i][0] += a * bv.x;
                ac[i][1] += a * bv.y;
                ac[i][2] += a * bv.z;
                ac[i][3] += a * bv.w;
            }
        }
        __syncthreads();
    }

    float4 bb = *(const float4*)(bias + tn);
#pragma unroll
    for (int i = 0; i < 8; i++) {
        int gr = m0 + tm + i;
        if (gr < NN) {
            float dv = g_dinv[gr];
            float sn = dv * dv;
            float4 o = make_float4(ac[i][0], ac[i][1], ac[i][2], ac[i][3]);
            *(float4*)(g_bufA + (size_t)gr * DD + tn) = o;
            float4 a2 = make_float4(o.x * sn + bb.x, o.y * sn + bb.y,
                                    o.z * sn + bb.z, o.w * sn + bb.w);
            *(float4*)(g_bufB + (size_t)gr * DD + tn) = a2;
        }
    }
}

// -------- edge scatter: g_bufB[dst] += norm * g_bufA[src]
// One warp per edge; 4 iterations of fully-coalesced 128B scalar red.
__global__ __launch_bounds__(256) void k_scatter() {
    int gid  = blockIdx.x * blockDim.x + threadIdx.x;
    int e    = gid >> 5;
    if (e >= NE) return;
    int lane = gid & 31;
    int s = g_src[e], d = g_dst[e];
    float nm = g_norm[e];
    const float* ps = g_bufA + (size_t)s * DD;
    float*       pd = g_bufB + (size_t)d * DD;
#pragma unroll
    for (int c = 0; c < DD; c += 32) {
        float v = ps[c + lane] * nm;
        atomicAdd(pd + c + lane, v);
    }
}

// -------- pooled sum: g_pool[batch[n]] += h[n]
__global__ __launch_bounds__(256) void k_pool(const int* __restrict__ batch) {
    int gid = blockIdx.x * blockDim.x + threadIdx.x;
    int n   = gid >> 5;
    if (n >= NN) return;
    int lane = gid & 31;
    int g = batch[n];
    const float* ph = g_bufB + (size_t)n * DD;
    float*       pp = g_pool + g * DD;
#pragma unroll
    for (int c = 0; c < DD; c += 32) {
        atomicAdd(pp + c + lane, ph[c + lane]);
    }
}

// -------- head: out[g] = (pool[g] @ fcW + cnt[g]*fcb) / max(cnt[g],1)
__global__ void k_final(const float* __restrict__ fcW,
                        const float* __restrict__ fcb,
                        float* __restrict__ out) {
    int g = blockIdx.x;
    int o = threadIdx.x;   // 32
    float c = g_cnt[g];
    float s = 0.0f;
#pragma unroll 4
    for (int k = 0; k < DD; k++) s += g_pool[g * DD + k] * fcW[k * DOUT + o];
    out[g * DOUT + o] = (s + c * fcb[o]) / fmaxf(c, 1.0f);
}

extern "C" void kernel_launch(void* const* d_in, const int* in_sizes, int n_in,
                              void* d_out, int out_size) {
    const float* x     = (const float*)d_in[0];
    const int*   ei    = (const int*)d_in[1];
    const int*   batch = (const int*)d_in[2];
    const float* W1 = (const float*)d_in[3],  *b1 = (const float*)d_in[4];
    const float* W2 = (const float*)d_in[5],  *b2 = (const float*)d_in[6];
    const float* W3 = (const float*)d_in[7],  *b3 = (const float*)d_in[8];
    const float* W4 = (const float*)d_in[9],  *b4 = (const float*)d_in[10];
    const float* fcW = (const float*)d_in[11], *fcb = (const float*)d_in[12];
    float* out = (float*)d_out;

    const int TB = 256;
    k_init<<<(NN + TB - 1) / TB, TB>>>();
    k_edges<<<(NE + TB - 1) / TB, TB>>>(ei);
    k_dinv<<<(NN + TB - 1) / TB, TB>>>(batch);
    k_norm<<<(NE + TB - 1) / TB, TB>>>();

    const int GEMM_BLOCKS = (NN + 63) / 64;                 // 782
    const int SCAT_BLOCKS = (NE * 32) / TB;                 // 75000

    k_gemm<true ><<<GEMM_BLOCKS, TB>>>(x, W1, b1);
    k_scatter<<<SCAT_BLOCKS, TB>>>();
    k_gemm<false><<<GEMM_BLOCKS, TB>>>(x, W2, b2);
    k_scatter<<<SCAT_BLOCKS, TB>>>();
    k_gemm<false><<<GEMM_BLOCKS, TB>>>(x, W3, b3);
    k_scatter<<<SCAT_BLOCKS, TB>>>();
    k_gemm<false><<<GEMM_BLOCKS, TB>>>(x, W4, b4);
    k_scatter<<<SCAT_BLOCKS, TB>>>();

    k_pool<<<(NN * 32) / TB, TB>>>(batch);
    k_final<<<NG, DOUT>>>(fcW, fcb, out);
}

// round 4
// speedup vs baseline: 1.6878x; 1.6878x over previous
#include <cuda_runtime.h>
#include <cstddef>

#define NN 50000
#define NE 600000
#define DD 128
#define DOUT 32
#define NG 64

#define SCAN_BS 256
#define SCAN_NB ((NN + SCAN_BS - 1) / SCAN_BS)   // 196

// -------- scratch (device globals: allocation-free) --------
__device__ int   g_indeg[NN];          // incoming edge count (no self-loop)
__device__ float g_dinv[NN];
__device__ int   g_rowptr[NN];         // exclusive scan of indeg
__device__ int   g_fill[NN];
__device__ int   g_scan_tmp[NN];       // inclusive-scan scratch
__device__ int   g_bsum[SCAN_NB];
__device__ int   g_csr_src[NE];
__device__ float g_csr_norm[NE];
__device__ __align__(16) float g_bufA[(size_t)NN * DD];   // hW (gather source)
__device__ __align__(16) float g_bufB[(size_t)NN * DD];   // aggregated h
__device__ __align__(16) float g_pool[NG * DD];
__device__ float g_cnt[NG];

// ======== prep ========
__global__ void k_zero() {
    int i = blockIdx.x * blockDim.x + threadIdx.x;
    if (i < NN) { g_indeg[i] = 0; g_fill[i] = 0; }
    if (i < NG * DD) g_pool[i] = 0.0f;
    if (i < NG) g_cnt[i] = 0.0f;
}

__global__ void k_count(const int* __restrict__ ei) {
    int e = blockIdx.x * blockDim.x + threadIdx.x;
    if (e >= NE) return;
    atomicAdd(&g_indeg[ei[NE + e]], 1);
}

// --- 3-kernel exclusive scan of g_indeg -> g_rowptr ---
__global__ void k_scan1() {
    __shared__ int s[SCAN_BS];
    int i = blockIdx.x * SCAN_BS + threadIdx.x;
    int v = (i < NN) ? g_indeg[i] : 0;
    s[threadIdx.x] = v;
    __syncthreads();
#pragma unroll
    for (int off = 1; off < SCAN_BS; off <<= 1) {
        int t = (threadIdx.x >= off) ? s[threadIdx.x - off] : 0;
        __syncthreads();
        s[threadIdx.x] += t;
        __syncthreads();
    }
    if (i < NN) g_scan_tmp[i] = s[threadIdx.x];         // inclusive
    if (threadIdx.x == SCAN_BS - 1) g_bsum[blockIdx.x] = s[threadIdx.x];
}

__global__ void k_scan2() {
    __shared__ int s[SCAN_BS];
    int t = threadIdx.x;
    s[t] = (t < SCAN_NB) ? g_bsum[t] : 0;
    __syncthreads();
#pragma unroll
    for (int off = 1; off < SCAN_BS; off <<= 1) {
        int v = (t >= off) ? s[t - off] : 0;
        __syncthreads();
        s[t] += v;
        __syncthreads();
    }
    if (t < SCAN_NB) g_bsum[t] = s[t];                  // inclusive
}

__global__ void k_scan3() {
    int i = blockIdx.x * SCAN_BS + threadIdx.x;
    if (i >= NN) return;
    int base = (blockIdx.x > 0) ? g_bsum[blockIdx.x - 1] : 0;
    g_rowptr[i] = base + g_scan_tmp[i] - g_indeg[i];    // exclusive
}

__global__ void k_dinv(const int* __restrict__ batch) {
    int n = blockIdx.x * blockDim.x + threadIdx.x;
    if (n >= NN) return;
    g_dinv[n] = rsqrtf((float)g_indeg[n] + 1.0f);       // +1 self-loop
    atomicAdd(&g_cnt[batch[n]], 1.0f);
}

__global__ void k_fill(const int* __restrict__ ei) {
    int e = blockIdx.x * blockDim.x + threadIdx.x;
    if (e >= NE) return;
    int s = ei[e];
    int d = ei[NE + e];
    int pos = g_rowptr[d] + atomicAdd(&g_fill[d], 1);
    g_csr_src[pos]  = s;
    g_csr_norm[pos] = g_dinv[s] * g_dinv[d];
}

// ======== GEMM: g_bufA = A @ W  (A:[NN,128], W:[128,128]) ========
template <bool FIRST>
__global__ __launch_bounds__(256) void k_gemm(const float* __restrict__ X,
                                              const float* __restrict__ W) {
    const float* A = FIRST ? X : (const float*)g_bufB;
    __shared__ float As[64][33];
    __shared__ __align__(16) float Bs[32][DD];
    int t  = threadIdx.x;
    int m0 = blockIdx.x * 64;
    int tn = (t & 31) << 2;
    int tm = (t >> 5) << 3;

    float ac[8][4];
#pragma unroll
    for (int i = 0; i < 8; i++)
#pragma unroll
        for (int j = 0; j < 4; j++) ac[i][j] = 0.0f;

    for (int k0 = 0; k0 < DD; k0 += 32) {
#pragma unroll
        for (int i = 0; i < 2; i++) {
            int idx = t + i * 256;
            int r = idx >> 3, c4 = (idx & 7) << 2;
            int gr = m0 + r;
            float4 v = make_float4(0.f, 0.f, 0.f, 0.f);
            if (gr < NN) v = *(const float4*)(A + (size_t)gr * DD + k0 + c4);
            As[r][c4 + 0] = v.x; As[r][c4 + 1] = v.y;
            As[r][c4 + 2] = v.z; As[r][c4 + 3] = v.w;
        }
#pragma unroll
        for (int i = 0; i < 4; i++) {
            int idx = t + i * 256;
            int kr = idx >> 5, c4 = (idx & 31) << 2;
            *(float4*)(&Bs[kr][c4]) = *(const float4*)(W + (size_t)(k0 + kr) * DD + c4);
        }
        __syncthreads();
#pragma unroll
        for (int k = 0; k < 32; k++) {
            float4 bv = *(const float4*)(&Bs[k][tn]);
#pragma unroll
            for (int i = 0; i < 8; i++) {
                float a = As[tm + i][k];
                ac[i][0] += a * bv.x;
                ac[i][1] += a * bv.y;
                ac[i][2] += a * bv.z;
                ac[i][3] += a * bv.w;
            }
        }
        __syncthreads();
    }

#pragma unroll
    for (int i = 0; i < 8; i++) {
        int gr = m0 + tm + i;
        if (gr < NN)
            *(float4*)(g_bufA + (size_t)gr * DD + tn) =
                make_float4(ac[i][0], ac[i][1], ac[i][2], ac[i][3]);
    }
}

// ======== aggregate: bufB[n] = dinv[n]^2*bufA[n] + bias + sum_e norm*bufA[src] ========
__global__ __launch_bounds__(256) void k_aggregate(const float* __restrict__ bias) {
    int gid  = blockIdx.x * blockDim.x + threadIdx.x;
    int n    = gid >> 5;
    if (n >= NN) return;
    int lane = gid & 31;
    int col  = lane << 2;

    float dv = g_dinv[n];
    float sn = dv * dv;
    float4 self = *(const float4*)(g_bufA + (size_t)n * DD + col);
    float4 bb   = *(const float4*)(bias + col);
    float4 acc  = make_float4(self.x * sn + bb.x, self.y * sn + bb.y,
                              self.z * sn + bb.z, self.w * sn + bb.w);

    int beg = g_rowptr[n];
    int end = beg + g_indeg[n];
    int e = beg;
    // unroll-by-2 for memory-level parallelism
    for (; e + 2 <= end; e += 2) {
        int   s0 = g_csr_src[e],     s1 = g_csr_src[e + 1];
        float n0 = g_csr_norm[e],    n1 = g_csr_norm[e + 1];
        float4 v0 = *(const float4*)(g_bufA + (size_t)s0 * DD + col);
        float4 v1 = *(const float4*)(g_bufA + (size_t)s1 * DD + col);
        acc.x += n0 * v0.x + n1 * v1.x;
        acc.y += n0 * v0.y + n1 * v1.y;
        acc.z += n0 * v0.z + n1 * v1.z;
        acc.w += n0 * v0.w + n1 * v1.w;
    }
    if (e < end) {
        int   s0 = g_csr_src[e];
        float n0 = g_csr_norm[e];
        float4 v0 = *(const float4*)(g_bufA + (size_t)s0 * DD + col);
        acc.x += n0 * v0.x; acc.y += n0 * v0.y;
        acc.z += n0 * v0.z; acc.w += n0 * v0.w;
    }
    *(float4*)(g_bufB + (size_t)n * DD + col) = acc;
}

// ======== pool: batch is sorted, so accumulate per-warp chunk and flush on change ========
#define POOL_CHUNK 16
__global__ __launch_bounds__(256) void k_pool(const int* __restrict__ batch) {
    int gid  = blockIdx.x * blockDim.x + threadIdx.x;
    int w    = gid >> 5;
    int n0   = w * POOL_CHUNK;
    if (n0 >= NN) return;
    int lane = gid & 31;
    int col  = lane << 2;

    int cur = batch[n0];
    float4 acc = make_float4(0.f, 0.f, 0.f, 0.f);
    for (int i = 0; i < POOL_CHUNK && n0 + i < NN; i++) {
        int n = n0 + i;
        int g = batch[n];
        if (g != cur) {
            float* p = g_pool + cur * DD + col;
            atomicAdd(p + 0, acc.x); atomicAdd(p + 1, acc.y);
            atomicAdd(p + 2, acc.z); atomicAdd(p + 3, acc.w);
            acc = make_float4(0.f, 0.f, 0.f, 0.f);
            cur = g;
        }
        float4 v = *(const float4*)(g_bufB + (size_t)n * DD + col);
        acc.x += v.x; acc.y += v.y; acc.z += v.z; acc.w += v.w;
    }
    float* p = g_pool + cur * DD + col;
    atomicAdd(p + 0, acc.x); atomicAdd(p + 1, acc.y);
    atomicAdd(p + 2, acc.z); atomicAdd(p + 3, acc.w);
}

// ======== head: out[g] = (pool[g] @ fcW + cnt[g]*fcb) / max(cnt[g],1) ========
__global__ void k_final(const float* __restrict__ fcW,
                        const float* __restrict__ fcb,
                        float* __restrict__ out) {
    int g = blockIdx.x;
    int o = threadIdx.x;   // 32
    float c = g_cnt[g];
    float s = 0.0f;
#pragma unroll 4
    for (int k = 0; k < DD; k++) s += g_pool[g * DD + k] * fcW[k * DOUT + o];
    out[g * DOUT + o] = (s + c * fcb[o]) / fmaxf(c, 1.0f);
}

extern "C" void kernel_launch(void* const* d_in, const int* in_sizes, int n_in,
                              void* d_out, int out_size) {
    const float* x     = (const float*)d_in[0];
    const int*   ei    = (const int*)d_in[1];
    const int*   batch = (const int*)d_in[2];
    const float* W1 = (const float*)d_in[3],  *b1 = (const float*)d_in[4];
    const float* W2 = (const float*)d_in[5],  *b2 = (const float*)d_in[6];
    const float* W3 = (const float*)d_in[7],  *b3 = (const float*)d_in[8];
    const float* W4 = (const float*)d_in[9],  *b4 = (const float*)d_in[10];
    const float* fcW = (const float*)d_in[11], *fcb = (const float*)d_in[12];
    float* out = (float*)d_out;

    const int TB = 256;
    k_zero <<<(NG * DD + TB - 1) / TB + ((NN > NG * DD) ? (NN - NG * DD + TB - 1) / TB : 0) + 0, TB>>>();
    // simpler: ensure grid covers max(NN, NG*DD)
    // (the line above already covers NN since NN > NG*DD; recompute plainly:)
    k_count<<<(NE + TB - 1) / TB, TB>>>(ei);
    k_scan1<<<SCAN_NB, SCAN_BS>>>();
    k_scan2<<<1, SCAN_BS>>>();
    k_scan3<<<SCAN_NB, SCAN_BS>>>();
    k_dinv <<<(NN + TB - 1) / TB, TB>>>(batch);
    k_fill <<<(NE + TB - 1) / TB, TB>>>(ei);

    const int GEMM_BLOCKS = (NN + 63) / 64;          // 782
    const int AGG_BLOCKS  = (NN * 32 + TB - 1) / TB; // 6250

    k_gemm<true ><<<GEMM_BLOCKS, TB>>>(x, W1);
    k_aggregate<<<AGG_BLOCKS, TB>>>(b1);
    k_gemm<false><<<GEMM_BLOCKS, TB>>>(x, W2);
    k_aggregate<<<AGG_BLOCKS, TB>>>(b2);
    k_gemm<false><<<GEMM_BLOCKS, TB>>>(x, W3);
    k_aggregate<<<AGG_BLOCKS, TB>>>(b3);
    k_gemm<false><<<GEMM_BLOCKS, TB>>>(x, W4);
    k_aggregate<<<AGG_BLOCKS, TB>>>(b4);

    k_pool<<<(NN / POOL_CHUNK * 32 + TB - 1) / TB, TB>>>(batch);
    k_final<<<NG, DOUT>>>(fcW, fcb, out);
}

// round 6
// speedup vs baseline: 2.9871x; 1.7699x over previous
#include <cuda_runtime.h>
#include <cstddef>

#define NN 50000
#define NE 600000
#define DD 128
#define DC 32          // collapsed output width
#define NG 64

#define SCAN_BS 256
#define SCAN_NB ((NN + SCAN_BS - 1) / SCAN_BS)   // 196

// -------- scratch (device globals: allocation-free) --------
// NOTE: device globals are referenced ONLY inside kernels (never passed as
// kernel args from host — host-side symbol address is invalid on device).
__device__ int   g_indeg[NN];
__device__ float g_dinv[NN];
__device__ int   g_rowptr[NN];
__device__ int   g_fill[NN];
__device__ int   g_scan_tmp[NN];
__device__ int   g_bsum[SCAN_NB];
__device__ int   g_csr_src[NE];
__device__ float g_csr_norm[NE];
__device__ float g_u1[NN], g_u2[NN], g_u3[NN];
__device__ __align__(16) float g_M1[DD * DC];
__device__ __align__(16) float g_M2[DD * DC];
__device__ __align__(16) float g_M3[DD * DC];
__device__ __align__(16) float g_Wc[DD * DC];
__device__ float g_cv[4 * DC];
__device__ __align__(16) float g_Y0[(size_t)NN * DC];
__device__ __align__(16) float g_Y1[(size_t)NN * DC];
__device__ float g_pool[NG * DC];
__device__ float g_usum[NG * 3];
__device__ float g_cnt[NG];

// ======== prep ========
__global__ void k_zero() {
    int i = blockIdx.x * blockDim.x + threadIdx.x;
    if (i < NN) { g_indeg[i] = 0; g_fill[i] = 0; }
    if (i < NG * DC) g_pool[i] = 0.0f;
    if (i < NG * 3) g_usum[i] = 0.0f;
    if (i < NG) g_cnt[i] = 0.0f;
}

__global__ void k_count(const int* __restrict__ ei) {
    int e = blockIdx.x * blockDim.x + threadIdx.x;
    if (e >= NE) return;
    atomicAdd(&g_indeg[ei[NE + e]], 1);
}

__global__ void k_scan1() {
    __shared__ int s[SCAN_BS];
    int i = blockIdx.x * SCAN_BS + threadIdx.x;
    int v = (i < NN) ? g_indeg[i] : 0;
    s[threadIdx.x] = v;
    __syncthreads();
#pragma unroll
    for (int off = 1; off < SCAN_BS; off <<= 1) {
        int t = (threadIdx.x >= off) ? s[threadIdx.x - off] : 0;
        __syncthreads();
        s[threadIdx.x] += t;
        __syncthreads();
    }
    if (i < NN) g_scan_tmp[i] = s[threadIdx.x];
    if (threadIdx.x == SCAN_BS - 1) g_bsum[blockIdx.x] = s[threadIdx.x];
}

__global__ void k_scan2() {
    __shared__ int s[SCAN_BS];
    int t = threadIdx.x;
    s[t] = (t < SCAN_NB) ? g_bsum[t] : 0;
    __syncthreads();
#pragma unroll
    for (int off = 1; off < SCAN_BS; off <<= 1) {
        int v = (t >= off) ? s[t - off] : 0;
        __syncthreads();
        s[t] += v;
        __syncthreads();
    }
    if (t < SCAN_NB) g_bsum[t] = s[t];
}

__global__ void k_scan3() {
    int i = blockIdx.x * SCAN_BS + threadIdx.x;
    if (i >= NN) return;
    int base = (blockIdx.x > 0) ? g_bsum[blockIdx.x - 1] : 0;
    g_rowptr[i] = base + g_scan_tmp[i] - g_indeg[i];
}

__global__ void k_dinv(const int* __restrict__ batch) {
    int n = blockIdx.x * blockDim.x + threadIdx.x;
    if (n >= NN) return;
    g_dinv[n] = rsqrtf((float)g_indeg[n] + 1.0f);
    atomicAdd(&g_cnt[batch[n]], 1.0f);
}

__global__ void k_fill(const int* __restrict__ ei) {
    int e = blockIdx.x * blockDim.x + threadIdx.x;
    if (e >= NE) return;
    int s = ei[e];
    int d = ei[NE + e];
    int pos = g_rowptr[d] + atomicAdd(&g_fill[d], 1);
    g_csr_src[pos]  = s;
    g_csr_norm[pos] = g_dinv[s] * g_dinv[d];
}

// ======== weight chain: C[128,32] = A[128,128] @ B[128,32] ========
// bsel: 0 = Bext (fcW), 1 = g_M3, 2 = g_M2, 3 = g_M1
// csel: 0 = g_M3, 1 = g_M2, 2 = g_M1, 3 = g_Wc
__global__ void k_mm(const float* __restrict__ A, const float* __restrict__ Bext,
                     int bsel, int csel) {
    const float* B = (bsel == 0) ? Bext : (bsel == 1) ? g_M3 : (bsel == 2) ? g_M2 : g_M1;
    float*       C = (csel == 0) ? g_M3 : (csel == 1) ? g_M2 : (csel == 2) ? g_M1 : g_Wc;
    int t = blockIdx.x * blockDim.x + threadIdx.x;   // 16 blocks * 256 = 4096
    int r = t >> 5, c = t & 31;
    float s = 0.0f;
#pragma unroll 8
    for (int k = 0; k < DD; k++) s += A[r * DD + k] * B[k * DC + c];
    C[r * DC + c] = s;
}

// c_i = b_i^T M_i  (M4 = fcW)
__global__ void k_cvec(const float* __restrict__ b1, const float* __restrict__ b2,
                       const float* __restrict__ b3, const float* __restrict__ b4,
                       const float* __restrict__ fcW) {
    int t = threadIdx.x;              // 128 threads
    int i = t >> 5, c = t & 31;
    const float* b = (i == 0) ? b1 : (i == 1) ? b2 : (i == 2) ? b3 : b4;
    const float* M = (i == 0) ? g_M1 : (i == 1) ? g_M2 : (i == 2) ? g_M3 : fcW;
    float s = 0.0f;
#pragma unroll 8
    for (int k = 0; k < DD; k++) s += b[k] * M[k * DC + c];
    g_cv[i * DC + c] = s;
}

// ======== Y0 = X @ Wc   (X:[NN,128], Wc:[128,32]) ========
__global__ __launch_bounds__(256) void k_gemmY(const float* __restrict__ X) {
    __shared__ float Ws[DD][DC];      // 16 KB
    __shared__ float As[128][33];     // one 32-wide k-chunk of 128 rows
    int t  = threadIdx.x;
    int m0 = blockIdx.x * 128;
    int rb = t >> 3;                  // 0..31
    int cg = (t & 7) << 2;            // col group of 4

#pragma unroll
    for (int i = 0; i < 4; i++) {
        int lin = t + i * 256;        // 1024 float4 slots
        int r = lin >> 3, c4 = (lin & 7) << 2;
        *(float4*)&Ws[r][c4] = *(const float4*)(g_Wc + r * DC + c4);
    }

    float4 ac[4];
#pragma unroll
    for (int j = 0; j < 4; j++) ac[j] = make_float4(0.f, 0.f, 0.f, 0.f);

    for (int k0 = 0; k0 < DD; k0 += 32) {
        __syncthreads();
#pragma unroll
        for (int i = 0; i < 4; i++) {
            int lin = t + i * 256;
            int r = lin >> 3, c4 = (lin & 7) << 2;
            int gr = m0 + r;
            float4 v = make_float4(0.f, 0.f, 0.f, 0.f);
            if (gr < NN) v = *(const float4*)(X + (size_t)gr * DD + k0 + c4);
            As[r][c4 + 0] = v.x; As[r][c4 + 1] = v.y;
            As[r][c4 + 2] = v.z; As[r][c4 + 3] = v.w;
        }
        __syncthreads();
#pragma unroll
        for (int k = 0; k < 32; k++) {
            float4 wv = *(const float4*)&Ws[k0 + k][cg];
#pragma unroll
            for (int j = 0; j < 4; j++) {
                float a = As[rb + 32 * j][k];
                ac[j].x += a * wv.x; ac[j].y += a * wv.y;
                ac[j].z += a * wv.z; ac[j].w += a * wv.w;
            }
        }
    }

#pragma unroll
    for (int j = 0; j < 4; j++) {
        int gr = m0 + rb + 32 * j;
        if (gr < NN) *(float4*)(g_Y0 + (size_t)gr * DC + cg) = ac[j];
    }
}

// ======== scalar aggregate: u' = Â u ========
// stage 0: ones -> u1 ; stage 1: u1 -> u2 ; stage 2: u2 -> u3
__global__ void k_uagg(int stage) {
    int n = blockIdx.x * blockDim.x + threadIdx.x;
    if (n >= NN) return;
    const float* uin = (stage == 1) ? g_u1 : (stage == 2) ? g_u2 : nullptr;
    float*      uout = (stage == 0) ? g_u1 : (stage == 1) ? g_u2 : g_u3;
    float dv = g_dinv[n];
    float acc = (stage == 0) ? dv * dv : dv * dv * uin[n];
    int beg = g_rowptr[n], end = beg + g_indeg[n];
    if (stage == 0) {
        for (int e = beg; e < end; e++) acc += g_csr_norm[e];
    } else {
        for (int e = beg; e < end; e++) acc += g_csr_norm[e] * uin[g_csr_src[e]];
    }
    uout[n] = acc;
}

// ======== vector aggregate (D=32): Yout = Â Yin ========
// flip 0: Y0 -> Y1 ; flip 1: Y1 -> Y0
__global__ __launch_bounds__(256) void k_vagg(int flip) {
    const float* Yin  = flip ? g_Y1 : g_Y0;
    float*       Yout = flip ? g_Y0 : g_Y1;
    int gid = blockIdx.x * blockDim.x + threadIdx.x;
    int n   = gid >> 5;
    if (n >= NN) return;
    int l = gid & 31;
    float dv  = g_dinv[n];
    float acc = dv * dv * Yin[(size_t)n * DC + l];
    int beg = g_rowptr[n], end = beg + g_indeg[n];
    int e = beg;
    for (; e + 4 <= end; e += 4) {
        int   s0 = g_csr_src[e],      s1 = g_csr_src[e + 1];
        int   s2 = g_csr_src[e + 2],  s3 = g_csr_src[e + 3];
        float w0 = g_csr_norm[e],     w1 = g_csr_norm[e + 1];
        float w2 = g_csr_norm[e + 2], w3 = g_csr_norm[e + 3];
        acc += w0 * Yin[(size_t)s0 * DC + l] + w1 * Yin[(size_t)s1 * DC + l]
             + w2 * Yin[(size_t)s2 * DC + l] + w3 * Yin[(size_t)s3 * DC + l];
    }
    for (; e < end; e++)
        acc += g_csr_norm[e] * Yin[(size_t)g_csr_src[e] * DC + l];
    Yout[(size_t)n * DC + l] = acc;
}

// ======== pooled sums (batch sorted -> chunked accumulate, rare flushes) ========
#define POOL_CHUNK 16
__global__ __launch_bounds__(256) void k_pool(const int* __restrict__ batch) {
    int gid = blockIdx.x * blockDim.x + threadIdx.x;
    int w   = gid >> 5;
    int n0  = w * POOL_CHUNK;
    if (n0 >= NN) return;
    int l = gid & 31;
    int cur = batch[n0];
    float acc = 0.0f;
    for (int i = 0; i < POOL_CHUNK && n0 + i < NN; i++) {
        int n = n0 + i;
        int g = batch[n];
        if (g != cur) {
            atomicAdd(&g_pool[cur * DC + l], acc);
            acc = 0.0f; cur = g;
        }
        acc += g_Y0[(size_t)n * DC + l];   // final Z lives in g_Y0
    }
    atomicAdd(&g_pool[cur * DC + l], acc);
}

__global__ void k_upool(const int* __restrict__ batch) {
    int t  = blockIdx.x * blockDim.x + threadIdx.x;
    int n0 = t * POOL_CHUNK;
    if (n0 >= NN) return;
    int cur = batch[n0];
    float s1 = 0.f, s2 = 0.f, s3 = 0.f;
    for (int i = 0; i < POOL_CHUNK && n0 + i < NN; i++) {
        int n = n0 + i;
        int g = batch[n];
        if (g != cur) {
            atomicAdd(&g_usum[cur * 3 + 0], s1);
            atomicAdd(&g_usum[cur * 3 + 1], s2);
            atomicAdd(&g_usum[cur * 3 + 2], s3);
            s1 = s2 = s3 = 0.f; cur = g;
        }
        s1 += g_u1[n]; s2 += g_u2[n]; s3 += g_u3[n];
    }
    atomicAdd(&g_usum[cur * 3 + 0], s1);
    atomicAdd(&g_usum[cur * 3 + 1], s2);
    atomicAdd(&g_usum[cur * 3 + 2], s3);
}

// ======== final: mean pool + rank-1 bias terms ========
__global__ void k_final(const float* __restrict__ fcb, float* __restrict__ out) {
    int g = blockIdx.x;
    int c = threadIdx.x;   // 32
    float cnt = g_cnt[g];
    float v = g_pool[g * DC + c]
            + g_usum[g * 3 + 2] * g_cv[0 * DC + c]      // u3 * (b1ᵀ W2W3W4 fcW)
            + g_usum[g * 3 + 1] * g_cv[1 * DC + c]      // u2 * (b2ᵀ W3W4 fcW)
            + g_usum[g * 3 + 0] * g_cv[2 * DC + c]      // u1 * (b3ᵀ W4 fcW)
            + cnt * (g_cv[3 * DC + c] + fcb[c]);        // 1  * (b4ᵀ fcW + fcb)
    out[g * DC + c] = v / fmaxf(cnt, 1.0f);
}

extern "C" void kernel_launch(void* const* d_in, const int* in_sizes, int n_in,
                              void* d_out, int out_size) {
    const float* x     = (const float*)d_in[0];
    const int*   ei    = (const int*)d_in[1];
    const int*   batch = (const int*)d_in[2];
    const float* W1 = (const float*)d_in[3],  *b1 = (const float*)d_in[4];
    const float* W2 = (const float*)d_in[5],  *b2 = (const float*)d_in[6];
    const float* W3 = (const float*)d_in[7],  *b3 = (const float*)d_in[8];
    const float* W4 = (const float*)d_in[9],  *b4 = (const float*)d_in[10];
    const float* fcW = (const float*)d_in[11], *fcb = (const float*)d_in[12];
    float* out = (float*)d_out;

    const int TB = 256;
    // CSR + norm prep
    k_zero <<<(NN + TB - 1) / TB, TB>>>();
    k_count<<<(NE + TB - 1) / TB, TB>>>(ei);
    k_scan1<<<SCAN_NB, SCAN_BS>>>();
    k_scan2<<<1, SCAN_BS>>>();
    k_scan3<<<SCAN_NB, SCAN_BS>>>();
    k_dinv <<<(NN + TB - 1) / TB, TB>>>(batch);
    k_fill <<<(NE + TB - 1) / TB, TB>>>(ei);

    // collapse weight chain: M3 = W4 fcW; M2 = W3 M3; M1 = W2 M2; Wc = W1 M1
    k_mm<<<16, TB>>>(W4, fcW, 0, 0);
    k_mm<<<16, TB>>>(W3, nullptr, 1, 1);
    k_mm<<<16, TB>>>(W2, nullptr, 2, 2);
    k_mm<<<16, TB>>>(W1, nullptr, 3, 3);
    k_cvec<<<1, 128>>>(b1, b2, b3, b4, fcW);

    // Y0 = X @ Wc
    k_gemmY<<<(NN + 127) / 128, TB>>>(x);

    // u_k = Â^k 1
    k_uagg<<<(NN + TB - 1) / TB, TB>>>(0);
    k_uagg<<<(NN + TB - 1) / TB, TB>>>(1);
    k_uagg<<<(NN + TB - 1) / TB, TB>>>(2);

    // Z = Â^4 Y0   (ping-pong, ends in g_Y0)
    const int AGG_BLOCKS = (NN * 32 + TB - 1) / TB;   // 6250
    k_vagg<<<AGG_BLOCKS, TB>>>(0);
    k_vagg<<<AGG_BLOCKS, TB>>>(1);
    k_vagg<<<AGG_BLOCKS, TB>>>(0);
    k_vagg<<<AGG_BLOCKS, TB>>>(1);

    // pooling + final
    const int NCHUNK = (NN + POOL_CHUNK - 1) / POOL_CHUNK;  // 3125
    k_pool <<<(NCHUNK * 32 + TB - 1) / TB, TB>>>(batch);
    k_upool<<<(NCHUNK + TB - 1) / TB, TB>>>(batch);
    k_final<<<NG, DC>>>(fcb, out);
}